// round 3
// baseline (speedup 1.0000x reference)
#include <cuda_runtime.h>

#define B_ 16
#define T_ 1024
#define D_ 1024
#define H_ 256
#define R_ 64
#define N_ 8

#define TT 64      // T rows per block tile
#define KC 32      // k-chunk

// Scratch (no allocations allowed -> device globals)
__device__ float g_losses[N_ * B_];
__device__ int   g_adp[B_];
__device__ float g_mid[(size_t)B_ * T_ * R_];

// ---------------------------------------------------------------------------
__global__ void zero_losses_kernel() {
    int i = threadIdx.x;
    if (i < N_ * B_) g_losses[i] = 0.f;
}

// ---------------------------------------------------------------------------
// Per (n, b, t-tile): h = relu(x@W_enc[n]+b_enc[n]) in SMEM, then
// recon = h@W_dec[n]+b_dec[n] in 256-col chunks, accumulate sum((recon-x)^2).
// Dynamic smem: hs[TT][H_] + ws[KC][256] + xs[TT][KC]
__global__ void disc_loss_kernel(const float* __restrict__ x,
                                 const float* __restrict__ W_enc,
                                 const float* __restrict__ b_enc,
                                 const float* __restrict__ W_dec,
                                 const float* __restrict__ b_dec) {
    extern __shared__ float smem[];
    float* hs = smem;                  // TT*H_  = 16384
    float* ws = hs + TT * H_;          // KC*256 =  8192
    float* xs = ws + KC * 256;         // TT*KC  =  2048

    const int n  = blockIdx.z;
    const int b  = blockIdx.y;
    const int t0 = blockIdx.x * TT;
    const int tid = threadIdx.x;
    const int tr = tid >> 5;           // 0..7  -> rows tr*8 .. tr*8+7
    const int tc = tid & 31;           // 0..31 -> cols tc + 32*j

    const float* xb = x + ((size_t)b * T_ + t0) * D_;

    float acc[8][8];
#pragma unroll
    for (int i = 0; i < 8; i++)
#pragma unroll
        for (int j = 0; j < 8; j++) acc[i][j] = 0.f;

    // ---- Phase 1: h tile ----
    for (int k0 = 0; k0 < D_; k0 += KC) {
        __syncthreads();
#pragma unroll
        for (int l = 0; l < (TT * KC) / 256; l++) {
            int idx = tid + l * 256;
            xs[idx] = xb[(size_t)(idx >> 5) * D_ + k0 + (idx & 31)];
        }
        const float* we = W_enc + ((size_t)n * D_ + k0) * H_;  // contiguous KC*H_ chunk
#pragma unroll
        for (int l = 0; l < (KC * H_) / 256; l++) {
            int idx = tid + l * 256;
            ws[idx] = we[idx];
        }
        __syncthreads();
#pragma unroll
        for (int kk = 0; kk < KC; kk++) {
            float a[8], w[8];
#pragma unroll
            for (int i = 0; i < 8; i++) a[i] = xs[(tr * 8 + i) * KC + kk];
#pragma unroll
            for (int j = 0; j < 8; j++) w[j] = ws[kk * 256 + tc + 32 * j];
#pragma unroll
            for (int i = 0; i < 8; i++)
#pragma unroll
                for (int j = 0; j < 8; j++)
                    acc[i][j] = fmaf(a[i], w[j], acc[i][j]);
        }
    }
    // relu + bias -> hs
#pragma unroll
    for (int i = 0; i < 8; i++) {
        int row = tr * 8 + i;
#pragma unroll
        for (int j = 0; j < 8; j++) {
            int col = tc + 32 * j;
            float v = acc[i][j] + b_enc[n * H_ + col];
            hs[row * H_ + col] = v > 0.f ? v : 0.f;
        }
    }
    __syncthreads();

    // ---- Phase 2: recon chunks + squared error ----
    float sumsq = 0.f;
    for (int dc = 0; dc < D_ / 256; dc++) {
        int d0 = dc * 256;
        float racc[8][8];
#pragma unroll
        for (int i = 0; i < 8; i++)
#pragma unroll
            for (int j = 0; j < 8; j++) racc[i][j] = 0.f;

        for (int h0 = 0; h0 < H_; h0 += KC) {
            __syncthreads();
            const float* wd = W_dec + ((size_t)n * H_ + h0) * D_ + d0;
#pragma unroll
            for (int l = 0; l < (KC * 256) / 256; l++) {
                int idx = tid + l * 256;
                ws[idx] = wd[(size_t)(idx >> 8) * D_ + (idx & 255)];
            }
            __syncthreads();
#pragma unroll
            for (int kk = 0; kk < KC; kk++) {
                float a[8], w[8];
#pragma unroll
                for (int i = 0; i < 8; i++) a[i] = hs[(tr * 8 + i) * H_ + h0 + kk];
#pragma unroll
                for (int j = 0; j < 8; j++) w[j] = ws[kk * 256 + tc + 32 * j];
#pragma unroll
                for (int i = 0; i < 8; i++)
#pragma unroll
                    for (int j = 0; j < 8; j++)
                        racc[i][j] = fmaf(a[i], w[j], racc[i][j]);
            }
        }
#pragma unroll
        for (int i = 0; i < 8; i++) {
            int row = tr * 8 + i;
#pragma unroll
            for (int j = 0; j < 8; j++) {
                int col = tc + 32 * j;
                float recon = racc[i][j] + b_dec[n * D_ + d0 + col];
                float diff = recon - xb[(size_t)row * D_ + d0 + col];
                sumsq = fmaf(diff, diff, sumsq);
            }
        }
    }

    // block reduction -> one atomicAdd per block
#pragma unroll
    for (int o = 16; o > 0; o >>= 1)
        sumsq += __shfl_down_sync(0xffffffffu, sumsq, o);
    __shared__ float red[8];
    if (tc == 0) red[tr] = sumsq;
    __syncthreads();
    if (tid == 0) {
        float s = 0.f;
#pragma unroll
        for (int i = 0; i < 8; i++) s += red[i];
        atomicAdd(&g_losses[n * B_ + b], s);
    }
}

// ---------------------------------------------------------------------------
__global__ void argmin_kernel(const int* __restrict__ connected_idx) {
    int b = threadIdx.x;
    if (b < B_) {
        float best = g_losses[b];
        int bi = 0;
        for (int n = 1; n < N_; n++) {
            float v = g_losses[n * B_ + b];
            if (v < best) { best = v; bi = n; }
        }
        g_adp[b] = connected_idx[bi];
    }
}

// ---------------------------------------------------------------------------
// mid = relu(x @ W_down[adp[b]] + b_down[adp[b]])  -> g_mid[B,T,R]
__global__ void mid_kernel(const float* __restrict__ x,
                           const float* __restrict__ W_down,
                           const float* __restrict__ b_down) {
    __shared__ float xs[TT * KC];
    __shared__ float wd[KC * R_];
    const int b  = blockIdx.y;
    const int t0 = blockIdx.x * TT;
    const int tid = threadIdx.x;
    const int tr = tid >> 4;   // 0..15 -> rows tr*4 .. tr*4+3
    const int tc = tid & 15;   // cols tc + 16*j
    const int a = g_adp[b];

    const float* xb = x + ((size_t)b * T_ + t0) * D_;
    const float* Wd = W_down + (size_t)a * D_ * R_;

    float acc[4][4];
#pragma unroll
    for (int i = 0; i < 4; i++)
#pragma unroll
        for (int j = 0; j < 4; j++) acc[i][j] = 0.f;

    for (int k0 = 0; k0 < D_; k0 += KC) {
        __syncthreads();
#pragma unroll
        for (int l = 0; l < (TT * KC) / 256; l++) {
            int idx = tid + l * 256;
            xs[idx] = xb[(size_t)(idx >> 5) * D_ + k0 + (idx & 31)];
        }
#pragma unroll
        for (int l = 0; l < (KC * R_) / 256; l++) {
            int idx = tid + l * 256;
            wd[idx] = Wd[(size_t)(k0 + (idx >> 6)) * R_ + (idx & 63)];
        }
        __syncthreads();
#pragma unroll
        for (int kk = 0; kk < KC; kk++) {
            float av[4], wv[4];
#pragma unroll
            for (int i = 0; i < 4; i++) av[i] = xs[(tr * 4 + i) * KC + kk];
#pragma unroll
            for (int j = 0; j < 4; j++) wv[j] = wd[kk * R_ + tc + 16 * j];
#pragma unroll
            for (int i = 0; i < 4; i++)
#pragma unroll
                for (int j = 0; j < 4; j++)
                    acc[i][j] = fmaf(av[i], wv[j], acc[i][j]);
        }
    }
#pragma unroll
    for (int i = 0; i < 4; i++) {
        int row = tr * 4 + i;
#pragma unroll
        for (int j = 0; j < 4; j++) {
            int col = tc + 16 * j;
            float v = acc[i][j] + b_down[a * R_ + col];
            g_mid[((size_t)b * T_ + t0 + row) * R_ + col] = v > 0.f ? v : 0.f;
        }
    }
}

// ---------------------------------------------------------------------------
// out = x@W_base + b_base + mid@W_up[adp] + b_up[adp]
__global__ void out_kernel(const float* __restrict__ x,
                           const float* __restrict__ W_base,
                           const float* __restrict__ b_base,
                           const float* __restrict__ W_up,
                           const float* __restrict__ b_up,
                           float* __restrict__ out) {
    __shared__ float ws[KC * 256];
    __shared__ float xs[TT * KC];
    const int b  = blockIdx.z;
    const int d0 = blockIdx.y * 256;
    const int t0 = blockIdx.x * TT;
    const int tid = threadIdx.x;
    const int tr = tid >> 5;
    const int tc = tid & 31;
    const int a = g_adp[b];

    const float* xb = x + ((size_t)b * T_ + t0) * D_;

    float acc[8][8];
#pragma unroll
    for (int i = 0; i < 8; i++)
#pragma unroll
        for (int j = 0; j < 8; j++) acc[i][j] = 0.f;

    // base GEMM, k = D_
    for (int k0 = 0; k0 < D_; k0 += KC) {
        __syncthreads();
#pragma unroll
        for (int l = 0; l < (TT * KC) / 256; l++) {
            int idx = tid + l * 256;
            xs[idx] = xb[(size_t)(idx >> 5) * D_ + k0 + (idx & 31)];
        }
        const float* wb = W_base + (size_t)k0 * D_ + d0;
#pragma unroll
        for (int l = 0; l < (KC * 256) / 256; l++) {
            int idx = tid + l * 256;
            ws[idx] = wb[(size_t)(idx >> 8) * D_ + (idx & 255)];
        }
        __syncthreads();
#pragma unroll
        for (int kk = 0; kk < KC; kk++) {
            float av[8], wv[8];
#pragma unroll
            for (int i = 0; i < 8; i++) av[i] = xs[(tr * 8 + i) * KC + kk];
#pragma unroll
            for (int j = 0; j < 8; j++) wv[j] = ws[kk * 256 + tc + 32 * j];
#pragma unroll
            for (int i = 0; i < 8; i++)
#pragma unroll
                for (int j = 0; j < 8; j++)
                    acc[i][j] = fmaf(av[i], wv[j], acc[i][j]);
        }
    }

    // adapter part, k = R_
    const float* mb = g_mid + ((size_t)b * T_ + t0) * R_;
    const float* Wu = W_up + (size_t)a * R_ * D_;
    for (int k0 = 0; k0 < R_; k0 += KC) {
        __syncthreads();
#pragma unroll
        for (int l = 0; l < (TT * KC) / 256; l++) {
            int idx = tid + l * 256;
            xs[idx] = mb[(size_t)(idx >> 5) * R_ + k0 + (idx & 31)];
        }
        const float* wu = Wu + (size_t)k0 * D_ + d0;
#pragma unroll
        for (int l = 0; l < (KC * 256) / 256; l++) {
            int idx = tid + l * 256;
            ws[idx] = wu[(size_t)(idx >> 8) * D_ + (idx & 255)];
        }
        __syncthreads();
#pragma unroll
        for (int kk = 0; kk < KC; kk++) {
            float av[8], wv[8];
#pragma unroll
            for (int i = 0; i < 8; i++) av[i] = xs[(tr * 8 + i) * KC + kk];
#pragma unroll
            for (int j = 0; j < 8; j++) wv[j] = ws[kk * 256 + tc + 32 * j];
#pragma unroll
            for (int i = 0; i < 8; i++)
#pragma unroll
                for (int j = 0; j < 8; j++)
                    acc[i][j] = fmaf(av[i], wv[j], acc[i][j]);
        }
    }

    // epilogue
#pragma unroll
    for (int i = 0; i < 8; i++) {
        int row = tr * 8 + i;
#pragma unroll
        for (int j = 0; j < 8; j++) {
            int col = tc + 32 * j;
            float v = acc[i][j] + b_base[d0 + col] + b_up[a * D_ + d0 + col];
            out[((size_t)b * T_ + t0 + row) * D_ + d0 + col] = v;
        }
    }
}

// ---------------------------------------------------------------------------
extern "C" void kernel_launch(void* const* d_in, const int* in_sizes, int n_in,
                              void* d_out, int out_size) {
    const float* x       = (const float*)d_in[0];
    const float* W_base  = (const float*)d_in[1];
    const float* b_base  = (const float*)d_in[2];
    const float* W_enc   = (const float*)d_in[3];
    const float* b_enc   = (const float*)d_in[4];
    const float* W_dec   = (const float*)d_in[5];
    const float* b_dec   = (const float*)d_in[6];
    const float* W_down  = (const float*)d_in[7];
    const float* b_down  = (const float*)d_in[8];
    const float* W_up    = (const float*)d_in[9];
    const float* b_up    = (const float*)d_in[10];
    const int*   cidx    = (const int*)d_in[11];
    float* out = (float*)d_out;

    const int disc_smem = (TT * H_ + KC * 256 + TT * KC) * (int)sizeof(float); // 104 KB
    cudaFuncSetAttribute(disc_loss_kernel,
                         cudaFuncAttributeMaxDynamicSharedMemorySize, disc_smem);

    zero_losses_kernel<<<1, 128>>>();

    dim3 g1(T_ / TT, B_, N_);
    disc_loss_kernel<<<g1, 256, disc_smem>>>(x, W_enc, b_enc, W_dec, b_dec);

    argmin_kernel<<<1, 32>>>(cidx);

    dim3 g2(T_ / TT, B_);
    mid_kernel<<<g2, 256>>>(x, W_down, b_down);

    dim3 g3(T_ / TT, D_ / 256, B_);
    out_kernel<<<g3, 256>>>(x, W_base, b_base, W_up, b_up, out);
}